// round 15
// baseline (speedup 1.0000x reference)
#include <cuda_runtime.h>

// ContinuousWaveletTransform — collapsed form (see R8/R9 analysis):
//   out[b,s,n] = sum_{m=0}^{5} wr[m] * signal[b, n - wl_s + m]   (real part;
// harness output float32 = Re of reference complex64), zero-padded signal,
// wl_s = even(min(2048, int(64*scale_s))). Taps m>=6 are < 1.9e-8.
//
// R15: dispatch-floor shape variant. Evidence (R9/R10/R14: 5.57/5.31/5.18 us
// with issue% 36->17->12, all pipes <6%) says the kernel sits on a CTA-
// dispatch/ramp floor. VEC=8 halves CTA count vs R14 (1024 -> 512 blocks of
// 128 thr), 13-tap window as 7x LDG.64, zero-region early-out retained.

#define BATCH 4
#define SLEN 4096
#define NSC 32
#define TAPS 6
#define VEC 8
#define TOTAL (BATCH * NSC * SLEN)        // 524288 outputs
#define NTHREADS_TOT (TOTAL / VEC)        // 65536 threads
#define SIG_ELEMS (BATCH * SLEN)          // 16384 floats
#define WIN (VEC + TAPS - 1)              // 13-float load window

// wl per scale: even(min(2048, int(64 * linspace(1,64,32)[s]))), floor>=8
__constant__ int c_wl[NSC] = {
      64,  194,  324,  454,  584,  714,  844,  974,
    1104, 1234, 1364, 1494, 1624, 1754, 1884, 2014,
    2048, 2048, 2048, 2048, 2048, 2048, 2048, 2048,
    2048, 2048, 2048, 2048, 2048, 2048, 2048, 2048
};

__global__ __launch_bounds__(128)
void cwt_kernel_v8(const float* __restrict__ sig, float* __restrict__ out,
                   int sig_len, int out_elems) {
    // Re(w[m]) = exp(-0.5 m^2) * cos(2*pi*m/6)
    const float wr[TAPS] = { 1.0f,            0.30326533f,   -0.067667642f,
                            -0.011108997f,   -1.6773131e-4f,  1.8633266e-6f };

    int idx = blockIdx.x * blockDim.x + threadIdx.x;   // 0 .. NTHREADS_TOT-1

    int q  = idx & (SLEN / VEC - 1);       // bits [0,9): group of 8 n
    int s  = (idx >> 9) & (NSC - 1);       // bits [9,14)
    int b  = idx >> 14;                    // bits [14,16)
    int n0 = q * VEC;

    int wl = c_wl[s];
    int rowbase = b * SLEN;
    int base = n0 - wl;                    // lowest tap index (always even)

    float r[VEC] = {0.f, 0.f, 0.f, 0.f, 0.f, 0.f, 0.f, 0.f};
    int o = idx * VEC;

    if (base + (WIN - 1) < 0) {
        // entire 8-output group reads only zero-padding -> result is 0.
    } else if (base >= 0 && rowbase + base + (WIN - 1) < sig_len) {
        // fast path: all 13 taps in-bounds (max base+12 = 4040 < SLEN, wl>=64).
        // base even -> 8B-aligned window: 14 floats as 7 x LDG.64.
        const float2* p = reinterpret_cast<const float2*>(sig + rowbase + base);
        float x[WIN + 1];                  // 14 floats (x[13] unused)
        #pragma unroll
        for (int k = 0; k < (WIN + 1) / 2; k++) {
            float2 v = p[k];
            x[2 * k]     = v.x;
            x[2 * k + 1] = v.y;
        }
        #pragma unroll
        for (int j = 0; j < VEC; j++) {
            #pragma unroll
            for (int m = 0; m < TAPS; m++)
                r[j] = fmaf(wr[m], x[m + j], r[j]);
        }
    } else {
        // boundary: groups straddling the zero-pad edge. Fully guarded.
        #pragma unroll
        for (int j = 0; j < VEC; j++) {
            #pragma unroll
            for (int m = 0; m < TAPS; m++) {
                int jj = base + j + m;          // signal index within row
                int g  = rowbase + jj;
                if (jj >= 0 && jj < SLEN && g < sig_len)
                    r[j] = fmaf(wr[m], sig[g], r[j]);
            }
        }
    }

    if (o + VEC <= out_elems) {
        // d_out is cudaMalloc'd (256B aligned); o*4 is a 32B multiple.
        float4* po = reinterpret_cast<float4*>(out + o);
        po[0] = make_float4(r[0], r[1], r[2], r[3]);
        po[1] = make_float4(r[4], r[5], r[6], r[7]);
    } else {
        #pragma unroll
        for (int j = 0; j < VEC; j++)
            if (o + j < out_elems) out[o + j] = r[j];
    }
}

extern "C" void kernel_launch(void* const* d_in, const int* in_sizes, int n_in,
                              void* d_out, int out_size) {
    // Pick the signal input by size instead of trusting slot 0.
    const float* sig = (const float*)d_in[0];
    int sig_len = (n_in > 0) ? in_sizes[0] : SIG_ELEMS;
    for (int i = 0; i < n_in; i++) {
        if (in_sizes[i] >= SIG_ELEMS) { sig = (const float*)d_in[i]; sig_len = in_sizes[i]; break; }
    }
    if (sig_len > SIG_ELEMS) sig_len = SIG_ELEMS;

    int out_elems = out_size;               // 4-byte elements (empirically 524288)
    if (out_elems > TOTAL) out_elems = TOTAL;

    float* out = (float*)d_out;
    int threads = 128;
    int blocks = NTHREADS_TOT / threads;    // 512 (exact division)
    cwt_kernel_v8<<<blocks, threads>>>(sig, out, sig_len, out_elems);
}